// round 6
// baseline (speedup 1.0000x reference)
#include <cuda_runtime.h>
#include <cstdint>

#define B_DIM 4096
#define T_DIM 200
#define NEG_INF (-4294967295.0f)

// dynamic smem byte offsets (16B-aligned)
#define OFF_K    0        // keys fp32, 200 rows x 256B, 16B-granule XOR swizzle
#define OFF_W    51200    // wp2: 32 d2-rows x 304B padded (d-pair-interleaved weights)
#define OFF_QH   60928    // f32 qh[32]
#define OFF_W2   61056    // f32 w2[32]
#define OFF_SC   61184    // f32 scores[200]
#define OFF_OP   61984    // u64 opart[8][32] f32x2 partials
#define OFF_SINV 64032    // f32
#define SMEM_BYTES 64048

// weight byte offset within OFF_W for (d2, j): d2*304 + j*8 + (j>>3)*16
__device__ float g_wk2[2432];       // padded d-pair-interleaved wk = W1b - W1c
__device__ float g_qh[B_DIM * 32];  // b1 + q @ (W1a + W1c)

// ---------------- setup kernel: batch-invariant + query-side precompute ----------------
__global__ __launch_bounds__(256)
void setup_kernel(const float* __restrict__ query,
                  const float* __restrict__ W1,
                  const float* __restrict__ b1)
{
    __shared__ float wq[2048];       // W1a + W1c
    __shared__ float qs[32][64];
    const int tid = threadIdx.x;
    #pragma unroll 2
    for (int i = tid; i < 2048; i += 256) {
        float a = W1[i], c = W1[4096 + i];
        wq[i] = a + c;
    }
    if (blockIdx.x == 0) {
        // wk pairs: g_wk2 @ float idx d2*76 + j*2 + (j>>3)*4 = (wk[2d2][j], wk[2d2+1][j])
        for (int idx = tid; idx < 1024; idx += 256) {
            int d2 = idx >> 5, j = idx & 31;
            float w0 = W1[2048 + (2 * d2) * 32 + j] - W1[4096 + (2 * d2) * 32 + j];
            float w1 = W1[2048 + (2 * d2 + 1) * 32 + j] - W1[4096 + (2 * d2 + 1) * 32 + j];
            int fo = d2 * 76 + j * 2 + (j >> 3) * 4;
            g_wk2[fo] = w0;
            g_wk2[fo + 1] = w1;
        }
    }
    const int b0 = blockIdx.x * 32;
    for (int i = tid; i < 2048; i += 256)
        qs[i >> 6][i & 63] = query[(size_t)b0 * 64 + i];
    __syncthreads();
    const int j = tid & 31, grp = tid >> 5;
    const float bj = b1[j];
    #pragma unroll
    for (int i = 0; i < 4; i++) {
        const int bl = grp * 4 + i;
        float s = bj;
        #pragma unroll 16
        for (int d = 0; d < 64; d++)
            s = fmaf(qs[bl][d], wq[d * 32 + j], s);
        g_qh[(b0 + bl) * 32 + j] = s;
    }
}

// ---------------- main kernel ----------------
__global__ __launch_bounds__(256, 2)
void attn_pool_kernel(const float* __restrict__ keys,
                      const unsigned char* __restrict__ mask_raw,
                      const float* __restrict__ W2,
                      const float* __restrict__ b2,
                      float* __restrict__ out)
{
    extern __shared__ char sm[];
    float* smf = (float*)sm;
    const int b    = blockIdx.x;
    const int tid  = threadIdx.x;
    const int lane = tid & 31;
    const int tx   = tid & 3;        // j-block: j in [8*tx, 8*tx+8)
    const int ty   = tid >> 2;       // key-block: keys 4*ty .. 4*ty+3
    uint32_t sbase;
    asm("{ .reg .u64 t; cvta.to.shared.u64 t, %1; cvt.u32.u64 %0, t; }"
        : "=r"(sbase) : "l"(sm));

    // ---- async staging: keys (swizzled), wp2, qh row, w2 ----
    {
        const char* ksrc = (const char*)(keys + (size_t)b * (T_DIM * 64));
        #pragma unroll 4
        for (int i = tid; i < T_DIM * 16; i += 256) {
            int r = i >> 4, g = i & 15;
            int gs = g ^ ((r >> 2) & 7);
            uint32_t dst = sbase + OFF_K + r * 256 + (gs << 4);
            asm volatile("cp.async.cg.shared.global [%0], [%1], 16;"
                         :: "r"(dst), "l"(ksrc + i * 16));
        }
        #pragma unroll
        for (int i = tid; i < 608; i += 256)
            asm volatile("cp.async.cg.shared.global [%0], [%1], 16;"
                         :: "r"(sbase + OFF_W + i * 16), "l"((const char*)g_wk2 + i * 16));
        if (tid < 8)
            asm volatile("cp.async.cg.shared.global [%0], [%1], 16;"
                         :: "r"(sbase + OFF_QH + tid * 16),
                            "l"((const char*)(g_qh + b * 32) + tid * 16));
        else if (tid < 16)
            asm volatile("cp.async.cg.shared.global [%0], [%1], 16;"
                         :: "r"(sbase + OFF_W2 + (tid - 8) * 16),
                            "l"((const char*)W2 + (tid - 8) * 16));
        asm volatile("cp.async.commit_group;" ::: "memory");
    }

    // ---- overlapped: mask dtype detect + mask/b2 prefetch ----
    int my_nz = 0;
    #pragma unroll
    for (int w = lane; w < 256; w += 32)
        my_nz |= mask_raw[4 * w + 1] | mask_raw[4 * w + 2] | mask_raw[4 * w + 3];
    const bool mode_u8 = __any_sync(0xffffffffu, my_nz != 0);
    const int* mask_i32 = (const int*)mask_raw;
    const float b2v = __ldg(b2);

    int mvalid = 0;
    if (tx == 0 && ty < 50) {
        #pragma unroll
        for (int t = 0; t < 4; t++) {
            const int mi = b * T_DIM + 4 * ty + t;
            const bool v = mode_u8 ? (mask_raw[mi] != 0) : (mask_i32[mi] != 0);
            mvalid |= (int)v << t;
        }
    }

    asm volatile("cp.async.wait_group 0;" ::: "memory");
    __syncthreads();

    // ====== score GEMM: 4 keys x 8 hidden, f32x2 packed along d (zero splats) ======
    if (ty < 50) {
        unsigned long long acc[32];  // acc[t*8+jj] = (even-d partial, odd-d partial)
        #pragma unroll
        for (int i = 0; i < 32; i++) acc[i] = 0ull;

        const uint32_t kb = sbase + OFF_K + (ty * 4) * 256;
        const uint32_t wb = sbase + OFF_W + tx * 80;
        const uint32_t sw = (uint32_t)((ty & 7) << 4);

        #pragma unroll 1
        for (int ch = 0; ch < 16; ch++) {      // 4 d = 2 d2 per ch
            const uint32_t go = ((uint32_t)(ch << 4)) ^ sw;
            unsigned long long ka[4][2];       // [t][d2 half]: (k[4ch+0],k[4ch+1]) , (k[4ch+2],k[4ch+3])
            #pragma unroll
            for (int t = 0; t < 4; t++)
                asm("ld.shared.v2.u64 {%0,%1},[%2];"
                    : "=l"(ka[t][0]), "=l"(ka[t][1]) : "r"(kb + t * 256 + go));
            unsigned long long w0[8], w1[8];   // jj 0..7 for d2=2ch and d2=2ch+1
            const uint32_t wr = wb + (2 * ch) * 304;
            asm("ld.shared.v2.u64 {%0,%1},[%2];" : "=l"(w0[0]), "=l"(w0[1]) : "r"(wr));
            asm("ld.shared.v2.u64 {%0,%1},[%2];" : "=l"(w0[2]), "=l"(w0[3]) : "r"(wr + 16));
            asm("ld.shared.v2.u64 {%0,%1},[%2];" : "=l"(w0[4]), "=l"(w0[5]) : "r"(wr + 32));
            asm("ld.shared.v2.u64 {%0,%1},[%2];" : "=l"(w0[6]), "=l"(w0[7]) : "r"(wr + 48));
            asm("ld.shared.v2.u64 {%0,%1},[%2];" : "=l"(w1[0]), "=l"(w1[1]) : "r"(wr + 304));
            asm("ld.shared.v2.u64 {%0,%1},[%2];" : "=l"(w1[2]), "=l"(w1[3]) : "r"(wr + 320));
            asm("ld.shared.v2.u64 {%0,%1},[%2];" : "=l"(w1[4]), "=l"(w1[5]) : "r"(wr + 336));
            asm("ld.shared.v2.u64 {%0,%1},[%2];" : "=l"(w1[6]), "=l"(w1[7]) : "r"(wr + 352));
            #pragma unroll
            for (int t = 0; t < 4; t++) {
                #pragma unroll
                for (int jj = 0; jj < 8; jj++)
                    asm("fma.rn.f32x2 %0,%1,%2,%0;"
                        : "+l"(acc[t * 8 + jj]) : "l"(ka[t][0]), "l"(w0[jj]));
            }
            #pragma unroll
            for (int t = 0; t < 4; t++) {
                #pragma unroll
                for (int jj = 0; jj < 8; jj++)
                    asm("fma.rn.f32x2 %0,%1,%2,%0;"
                        : "+l"(acc[t * 8 + jj]) : "l"(ka[t][1]), "l"(w1[jj]));
            }
        }

        float qhv[8], w2s[8];
        #pragma unroll
        for (int jj = 0; jj < 8; jj++) {
            qhv[jj] = smf[OFF_QH / 4 + 8 * tx + jj];
            w2s[jj] = smf[OFF_W2 / 4 + 8 * tx + jj];
        }

        const unsigned amask = __activemask();
        #pragma unroll
        for (int t = 0; t < 4; t++) {
            float s = 0.0f;
            #pragma unroll
            for (int jj = 0; jj < 8; jj++) {
                unsigned lo, hi;
                asm("mov.b64 {%0,%1},%2;" : "=r"(lo), "=r"(hi) : "l"(acc[t * 8 + jj]));
                float h = (__uint_as_float(lo) + __uint_as_float(hi)) + qhv[jj];
                float sg = __fdividef(1.0f, 1.0f + __expf(-h));
                s = fmaf(sg, w2s[jj], s);
            }
            s += __shfl_xor_sync(amask, s, 1);
            s += __shfl_xor_sync(amask, s, 2);
            if (tx == 0) {
                const int r = 4 * ty + t;
                smf[OFF_SC / 4 + r] = ((mvalid >> t) & 1) ? (s + b2v) : NEG_INF;
            }
        }
    }
    __syncthreads();

    // ---- softmax over 200 scores (warp 0) ----
    if (tid < 32) {
        float m = -1e38f;
        for (int t = lane; t < T_DIM; t += 32) m = fmaxf(m, smf[OFF_SC / 4 + t]);
        #pragma unroll
        for (int o = 16; o; o >>= 1) m = fmaxf(m, __shfl_xor_sync(0xffffffffu, m, o));
        float s = 0.0f;
        for (int t = lane; t < T_DIM; t += 32) {
            float e = __expf(smf[OFF_SC / 4 + t] - m);
            smf[OFF_SC / 4 + t] = e;
            s += e;
        }
        #pragma unroll
        for (int o = 16; o; o >>= 1) s += __shfl_xor_sync(0xffffffffu, s, o);
        if (lane == 0) smf[OFF_SINV / 4] = __fdividef(1.0f, s);
    }
    __syncthreads();

    // ---- weighted key sum, f32x2 over d-pairs: warp w handles keys [25w, 25w+25) ----
    {
        const int part = tid >> 5;
        unsigned long long acc = 0ull;
        const uint32_t kbase = sbase + OFF_K;
        const int t0 = part * 25;
        #pragma unroll 5
        for (int t = t0; t < t0 + 25; t++) {
            float p = smf[OFF_SC / 4 + t];
            unsigned long long pd;
            asm("mov.b64 %0,{%1,%1};" : "=l"(pd) : "r"(__float_as_uint(p)));
            int gs = (lane >> 1) ^ ((t >> 2) & 7);
            unsigned long long kv;
            asm("ld.shared.b64 %0,[%1];" : "=l"(kv)
                : "r"(kbase + t * 256 + (gs << 4) + ((lane & 1) << 3)));
            asm("fma.rn.f32x2 %0,%1,%2,%0;" : "+l"(acc) : "l"(kv), "l"(pd));
        }
        asm volatile("st.shared.b64 [%0],%1;"
                     :: "r"(sbase + OFF_OP + part * 256 + lane * 8), "l"(acc));
    }
    __syncthreads();
    if (tid < 64) {
        float r = 0.0f;
        #pragma unroll
        for (int p = 0; p < 8; p++)
            r += smf[(OFF_OP + p * 256) / 4 + tid];
        out[b * 64 + tid] = r * smf[OFF_SINV / 4];
    }
}

extern "C" void kernel_launch(void* const* d_in, const int* in_sizes, int n_in,
                              void* d_out, int out_size)
{
    const float*         query = (const float*)d_in[0];
    const float*         keys  = (const float*)d_in[1];
    const unsigned char* mask  = (const unsigned char*)d_in[2];
    const float*         W1    = (const float*)d_in[3];
    const float*         b1    = (const float*)d_in[4];
    const float*         W2    = (const float*)d_in[5];
    const float*         b2    = (const float*)d_in[6];
    float* out = (float*)d_out;

    setup_kernel<<<B_DIM / 32, 256>>>(query, W1, b1);
    cudaFuncSetAttribute(attn_pool_kernel,
                         cudaFuncAttributeMaxDynamicSharedMemorySize, SMEM_BYTES);
    attn_pool_kernel<<<B_DIM, 256, SMEM_BYTES>>>(keys, mask, W2, b2, out);
}

// round 7
// speedup vs baseline: 1.1919x; 1.1919x over previous
#include <cuda_runtime.h>
#include <cstdint>

#define B_DIM 4096
#define T_DIM 200
#define NEG_INF (-4294967295.0f)

// dynamic smem byte offsets
#define OFF_K    0        // f32 K[200][64]; 16B-chunk XOR swizzle: chunk' = chunk ^ (row&7)
#define OFF_W    51200    // f32 whl[64][72]: (hi,lo) interleaved per j, 8-float row pad
#define OFF_QH   69632    // f32 qh[32]
#define OFF_W2   69760    // f32 w2[32]
#define OFF_SC   69888    // f32 scores[200]
#define OFF_OP   70720    // u64 opart[8][32] f32x2 partials
#define OFF_SINV 72768    // f32
#define SMEM_BYTES 72784

__device__ float g_whl[64 * 72];    // tf32-split fused weights (hi,lo), padded rows
__device__ float g_qh[B_DIM * 32];  // b1 + q @ (W1a + W1c)

// ---------------- setup kernel ----------------
__global__ __launch_bounds__(256)
void setup_kernel(const float* __restrict__ query,
                  const float* __restrict__ W1,
                  const float* __restrict__ b1)
{
    __shared__ float wq[2048];       // W1a + W1c
    __shared__ float qs[32][64];
    const int tid = threadIdx.x;
    #pragma unroll 2
    for (int i = tid; i < 2048; i += 256) {
        float a = W1[i], c = W1[4096 + i];
        wq[i] = a + c;
    }
    if (blockIdx.x == 0) {
        for (int idx = tid; idx < 2048; idx += 256) {
            int d = idx >> 5, j = idx & 31;
            float w = W1[2048 + idx] - W1[4096 + idx];
            uint32_t hi;
            asm("cvt.rna.tf32.f32 %0, %1;" : "=r"(hi) : "f"(w));
            float lof = w - __uint_as_float(hi);
            uint32_t lo;
            asm("cvt.rna.tf32.f32 %0, %1;" : "=r"(lo) : "f"(lof));
            g_whl[d * 72 + 2 * j]     = __uint_as_float(hi);
            g_whl[d * 72 + 2 * j + 1] = __uint_as_float(lo);
        }
    }
    const int b0 = blockIdx.x * 32;
    for (int i = tid; i < 2048; i += 256)
        qs[i >> 6][i & 63] = query[(size_t)b0 * 64 + i];
    __syncthreads();
    const int j = tid & 31, grp = tid >> 5;
    const float bj = b1[j];
    #pragma unroll
    for (int i = 0; i < 4; i++) {
        const int bl = grp * 4 + i;
        float s = bj;
        #pragma unroll 16
        for (int d = 0; d < 64; d++)
            s = fmaf(qs[bl][d], wq[d * 32 + j], s);
        g_qh[(b0 + bl) * 32 + j] = s;
    }
}

static __device__ __forceinline__ float sigmoidf_fast(float h) {
    return __fdividef(1.0f, 1.0f + __expf(-h));
}

// ---------------- main kernel ----------------
__global__ __launch_bounds__(256, 3)
void attn_pool_kernel(const float* __restrict__ keys,
                      const unsigned char* __restrict__ mask_raw,
                      const float* __restrict__ W2,
                      const float* __restrict__ b2,
                      float* __restrict__ out)
{
    extern __shared__ char sm[];
    float* smf = (float*)sm;
    const int b    = blockIdx.x;
    const int tid  = threadIdx.x;
    const int lane = tid & 31;
    const int wid  = tid >> 5;
    const int g    = lane >> 2;      // fragment group id (row within tile)
    const int t4   = lane & 3;       // thread-in-group (col / k index)
    uint32_t sbase;
    asm("{ .reg .u64 t; cvta.to.shared.u64 t, %1; cvt.u32.u64 %0, t; }"
        : "=r"(sbase) : "l"(sm));

    // ---- async staging: keys (chunk-swizzled), split weights, qh, w2 ----
    {
        const char* ksrc = (const char*)(keys + (size_t)b * (T_DIM * 64));
        #pragma unroll 4
        for (int i = tid; i < T_DIM * 16; i += 256) {
            int r = i >> 4, c = i & 15;
            int cs = c ^ (r & 7);
            asm volatile("cp.async.cg.shared.global [%0], [%1], 16;"
                         :: "r"(sbase + OFF_K + r * 256 + cs * 16), "l"(ksrc + i * 16));
        }
        #pragma unroll 2
        for (int i = tid; i < 1152; i += 256)
            asm volatile("cp.async.cg.shared.global [%0], [%1], 16;"
                         :: "r"(sbase + OFF_W + i * 16), "l"((const char*)g_whl + i * 16));
        if (tid < 8)
            asm volatile("cp.async.cg.shared.global [%0], [%1], 16;"
                         :: "r"(sbase + OFF_QH + tid * 16),
                            "l"((const char*)(g_qh + b * 32) + tid * 16));
        else if (tid < 16)
            asm volatile("cp.async.cg.shared.global [%0], [%1], 16;"
                         :: "r"(sbase + OFF_W2 + (tid - 8) * 16),
                            "l"((const char*)W2 + (tid - 8) * 16));
        asm volatile("cp.async.commit_group;" ::: "memory");
    }

    // ---- overlapped: mask dtype detect + per-thread mask prefetch + b2 ----
    int my_nz = 0;
    #pragma unroll
    for (int w = lane; w < 256; w += 32)
        my_nz |= mask_raw[4 * w + 1] | mask_raw[4 * w + 2] | mask_raw[4 * w + 3];
    const bool mode_u8 = __any_sync(0xffffffffu, my_nz != 0);
    const int* mask_i32 = (const int*)mask_raw;
    const float b2v = __ldg(b2);

    const int nmt = (wid < 5) ? 2 : 1;   // m-tiles per warp: warp w -> tiles {w, w+8}
    int mval = 0;
    if (t4 == 0) {
        for (int mi = 0; mi < nmt; mi++) {
            const int m0 = (wid + 8 * mi) * 16;
            const int r0 = m0 + g, r1 = r0 + 8;
            bool v0 = mode_u8 ? (mask_raw[b * T_DIM + r0] != 0)
                              : (mask_i32[b * T_DIM + r0] != 0);
            mval |= (int)v0 << (2 * mi);
            if (r1 < T_DIM) {
                bool v1 = mode_u8 ? (mask_raw[b * T_DIM + r1] != 0)
                                  : (mask_i32[b * T_DIM + r1] != 0);
                mval |= (int)v1 << (2 * mi + 1);
            }
        }
    }

    asm volatile("cp.async.wait_group 0;" ::: "memory");
    __syncthreads();

    // ====== score GEMM via mma.sync m16n8k8 tf32, 3-product hi/lo split ======
    for (int mi = 0; mi < nmt; mi++) {
        const int m0 = (wid + 8 * mi) * 16;
        float c[4][4];
        #pragma unroll
        for (int n = 0; n < 4; n++)
            #pragma unroll
            for (int e = 0; e < 4; e++) c[n][e] = 0.0f;

        const uint32_t arow = sbase + OFF_K + (m0 + g) * 256 + t4 * 4;
        const bool r1ok = (m0 + g + 8) < T_DIM;

        #pragma unroll
        for (int ks = 0; ks < 8; ks++) {
            const uint32_t ch0 = (uint32_t)(((2 * ks) ^ g) << 4);
            const uint32_t ch1 = (uint32_t)(((2 * ks + 1) ^ g) << 4);
            float ar0, ar1 = 0.0f, ar2, ar3 = 0.0f;
            asm("ld.shared.f32 %0,[%1];" : "=f"(ar0) : "r"(arow + ch0));
            asm("ld.shared.f32 %0,[%1];" : "=f"(ar2) : "r"(arow + ch1));
            if (r1ok) {
                asm("ld.shared.f32 %0,[%1];" : "=f"(ar1) : "r"(arow + 2048 + ch0));
                asm("ld.shared.f32 %0,[%1];" : "=f"(ar3) : "r"(arow + 2048 + ch1));
            }
            uint32_t ah[4], al[4];
            float araw[4] = {ar0, ar1, ar2, ar3};
            #pragma unroll
            for (int e = 0; e < 4; e++) {
                asm("cvt.rna.tf32.f32 %0, %1;" : "=r"(ah[e]) : "f"(araw[e]));
                float lof = araw[e] - __uint_as_float(ah[e]);
                asm("cvt.rna.tf32.f32 %0, %1;" : "=r"(al[e]) : "f"(lof));
            }
            const uint32_t brow = sbase + OFF_W + (uint32_t)((8 * ks + t4) * 288 + g * 8);
            #pragma unroll
            for (int nt = 0; nt < 4; nt++) {
                float2 v0, v1;
                asm("ld.shared.v2.f32 {%0,%1},[%2];"
                    : "=f"(v0.x), "=f"(v0.y) : "r"(brow + nt * 64));
                asm("ld.shared.v2.f32 {%0,%1},[%2];"
                    : "=f"(v1.x), "=f"(v1.y) : "r"(brow + nt * 64 + 1152));
                const uint32_t bh0 = __float_as_uint(v0.x), bh1 = __float_as_uint(v1.x);
                const uint32_t bl0 = __float_as_uint(v0.y), bl1 = __float_as_uint(v1.y);
                asm volatile(
                    "mma.sync.aligned.m16n8k8.row.col.f32.tf32.tf32.f32 "
                    "{%0,%1,%2,%3}, {%4,%5,%6,%7}, {%8,%9}, {%0,%1,%2,%3};"
                    : "+f"(c[nt][0]), "+f"(c[nt][1]), "+f"(c[nt][2]), "+f"(c[nt][3])
                    : "r"(ah[0]), "r"(ah[1]), "r"(ah[2]), "r"(ah[3]), "r"(bh0), "r"(bh1));
                asm volatile(
                    "mma.sync.aligned.m16n8k8.row.col.f32.tf32.tf32.f32 "
                    "{%0,%1,%2,%3}, {%4,%5,%6,%7}, {%8,%9}, {%0,%1,%2,%3};"
                    : "+f"(c[nt][0]), "+f"(c[nt][1]), "+f"(c[nt][2]), "+f"(c[nt][3])
                    : "r"(ah[0]), "r"(ah[1]), "r"(ah[2]), "r"(ah[3]), "r"(bl0), "r"(bl1));
                asm volatile(
                    "mma.sync.aligned.m16n8k8.row.col.f32.tf32.tf32.f32 "
                    "{%0,%1,%2,%3}, {%4,%5,%6,%7}, {%8,%9}, {%0,%1,%2,%3};"
                    : "+f"(c[nt][0]), "+f"(c[nt][1]), "+f"(c[nt][2]), "+f"(c[nt][3])
                    : "r"(al[0]), "r"(al[1]), "r"(al[2]), "r"(al[3]), "r"(bh0), "r"(bh1));
            }
        }

        // epilogue: h = C + qh ; score partials, reduce over t4 lanes
        float s_lo = 0.0f, s_hi = 0.0f;
        #pragma unroll
        for (int nt = 0; nt < 4; nt++) {
            const int j0 = 8 * nt + 2 * t4;
            float2 qh2 = *(float2*)(sm + OFF_QH + j0 * 4);
            float2 w22 = *(float2*)(sm + OFF_W2 + j0 * 4);
            s_lo = fmaf(sigmoidf_fast(c[nt][0] + qh2.x), w22.x, s_lo);
            s_lo = fmaf(sigmoidf_fast(c[nt][1] + qh2.y), w22.y, s_lo);
            s_hi = fmaf(sigmoidf_fast(c[nt][2] + qh2.x), w22.x, s_hi);
            s_hi = fmaf(sigmoidf_fast(c[nt][3] + qh2.y), w22.y, s_hi);
        }
        s_lo += __shfl_xor_sync(0xffffffffu, s_lo, 1);
        s_lo += __shfl_xor_sync(0xffffffffu, s_lo, 2);
        s_hi += __shfl_xor_sync(0xffffffffu, s_hi, 1);
        s_hi += __shfl_xor_sync(0xffffffffu, s_hi, 2);
        if (t4 == 0) {
            const int r0 = m0 + g, r1 = r0 + 8;
            smf[OFF_SC / 4 + r0] = ((mval >> (2 * mi)) & 1) ? (s_lo + b2v) : NEG_INF;
            if (r1 < T_DIM)
                smf[OFF_SC / 4 + r1] = ((mval >> (2 * mi + 1)) & 1) ? (s_hi + b2v) : NEG_INF;
        }
    }
    __syncthreads();

    // ---- softmax over 200 scores (warp 0) ----
    if (tid < 32) {
        float m = -1e38f;
        for (int t = lane; t < T_DIM; t += 32) m = fmaxf(m, smf[OFF_SC / 4 + t]);
        #pragma unroll
        for (int o = 16; o; o >>= 1) m = fmaxf(m, __shfl_xor_sync(0xffffffffu, m, o));
        float s = 0.0f;
        for (int t = lane; t < T_DIM; t += 32) {
            float e = __expf(smf[OFF_SC / 4 + t] - m);
            smf[OFF_SC / 4 + t] = e;
            s += e;
        }
        #pragma unroll
        for (int o = 16; o; o >>= 1) s += __shfl_xor_sync(0xffffffffu, s, o);
        if (lane == 0) smf[OFF_SINV / 4] = __fdividef(1.0f, s);
    }
    __syncthreads();

    // ---- weighted key sum, f32x2 over d-pairs: warp w handles keys [25w, 25w+25) ----
    {
        const int part = tid >> 5;
        unsigned long long acc = 0ull;
        const uint32_t kbase = sbase + OFF_K;
        const int t0 = part * 25;
        #pragma unroll 5
        for (int t = t0; t < t0 + 25; t++) {
            float p = smf[OFF_SC / 4 + t];
            unsigned long long pd;
            asm("mov.b64 %0,{%1,%1};" : "=l"(pd) : "r"(__float_as_uint(p)));
            int gs = (lane >> 1) ^ (t & 7);
            unsigned long long kv;
            asm("ld.shared.b64 %0,[%1];" : "=l"(kv)
                : "r"(kbase + t * 256 + (gs << 4) + ((lane & 1) << 3)));
            asm("fma.rn.f32x2 %0,%1,%2,%0;" : "+l"(acc) : "l"(kv), "l"(pd));
        }
        asm volatile("st.shared.b64 [%0],%1;"
                     :: "r"(sbase + OFF_OP + part * 256 + lane * 8), "l"(acc));
    }
    __syncthreads();
    if (tid < 64) {
        float r = 0.0f;
        #pragma unroll
        for (int p = 0; p < 8; p++)
            r += smf[(OFF_OP + p * 256) / 4 + tid];
        out[b * 64 + tid] = r * smf[OFF_SINV / 4];
    }
}

extern "C" void kernel_launch(void* const* d_in, const int* in_sizes, int n_in,
                              void* d_out, int out_size)
{
    const float*         query = (const float*)d_in[0];
    const float*         keys  = (const float*)d_in[1];
    const unsigned char* mask  = (const unsigned char*)d_in[2];
    const float*         W1    = (const float*)d_in[3];
    const float*         b1    = (const float*)d_in[4];
    const float*         W2    = (const float*)d_in[5];
    const float*         b2    = (const float*)d_in[6];
    float* out = (float*)d_out;

    setup_kernel<<<B_DIM / 32, 256>>>(query, W1, b1);
    cudaFuncSetAttribute(attn_pool_kernel,
                         cudaFuncAttributeMaxDynamicSharedMemorySize, SMEM_BYTES);
    attn_pool_kernel<<<B_DIM, 256, SMEM_BYTES>>>(keys, mask, W2, b2, out);
}

// round 8
// speedup vs baseline: 1.3562x; 1.1379x over previous
#include <cuda_runtime.h>
#include <cuda_fp16.h>
#include <cstdint>

#define B_DIM 4096
#define T_DIM 200
#define NEG_INF (-4294967295.0f)

// dynamic smem byte offsets
#define OFF_K    0        // f32 K[200][64]; 16B-chunk XOR swizzle: chunk' = chunk ^ (row&7)
#define OFF_WHI  51200    // u32 whi[4][4][32][2] f16x2 B fragments (hi), 4KB
#define OFF_WLO  55296    // same, lo part, 4KB
#define OFF_QH   59392    // f32 qh[32]
#define OFF_W2   59520    // f32 w2[32]
#define OFF_SC   59648    // f32 scores[200]
#define OFF_OP   60480    // u64 opart[8][32] f32x2 partials
#define OFF_SINV 62528    // f32
#define SMEM_BYTES 62544

__device__ float    g_wq[2048];    // W1a + W1c  (for qh chain, read from L2)
__device__ uint32_t g_whi[1024];   // f16x2-packed fused weights, mma B-fragment order
__device__ uint32_t g_wlo[1024];   // f16 residuals

// ---------------- setup kernel: batch-invariant weight tables (1 block) ----------------
__global__ __launch_bounds__(256)
void setup_kernel(const float* __restrict__ W1)
{
    const int tid = threadIdx.x;
    #pragma unroll 2
    for (int i = tid; i < 2048; i += 256)
        g_wq[i] = W1[i] + W1[4096 + i];
    for (int idx = tid; idx < 1024; idx += 256) {
        int d2 = idx >> 5, j = idx & 31, k = 2 * d2;
        float w0 = W1[2048 + k * 32 + j] - W1[4096 + k * 32 + j];
        float w1 = W1[2048 + (k + 1) * 32 + j] - W1[4096 + (k + 1) * 32 + j];
        uint32_t hi, lo;
        asm("cvt.rn.f16x2.f32 %0, %1, %2;" : "=r"(hi) : "f"(w1), "f"(w0));
        float h0f = __half2float(__ushort_as_half((unsigned short)(hi & 0xFFFFu)));
        float h1f = __half2float(__ushort_as_half((unsigned short)(hi >> 16)));
        asm("cvt.rn.f16x2.f32 %0, %1, %2;" : "=r"(lo) : "f"(w1 - h1f), "f"(w0 - h0f));
        // B-fragment order: b0 k-pair (2t4,2t4+1), b1 k-pair (2t4+8,2t4+9), n = g
        int ks = d2 >> 3, k2 = d2 & 7, t4 = k2 & 3, sel = k2 >> 2;
        int word = ((ks * 4 + t4) * 32 + j) * 2 + sel;
        g_whi[word] = hi;
        g_wlo[word] = lo;
    }
}

static __device__ __forceinline__ float sigmoidf_fast(float h) {
    return __fdividef(1.0f, 1.0f + __expf(-h));
}

// ---------------- main kernel ----------------
__global__ __launch_bounds__(256, 3)
void attn_pool_kernel(const float* __restrict__ query,
                      const float* __restrict__ keys,
                      const unsigned char* __restrict__ mask_raw,
                      const float* __restrict__ b1,
                      const float* __restrict__ W2,
                      const float* __restrict__ b2,
                      float* __restrict__ out)
{
    extern __shared__ char sm[];
    float* smf = (float*)sm;
    const int b    = blockIdx.x;
    const int tid  = threadIdx.x;
    const int lane = tid & 31;
    const int wid  = tid >> 5;
    const int g    = lane >> 2;      // fragment group id
    const int t4   = lane & 3;       // thread-in-group
    uint32_t sbase;
    asm("{ .reg .u64 t; cvta.to.shared.u64 t, %1; cvt.u32.u64 %0, t; }"
        : "=r"(sbase) : "l"(sm));

    // ---- async staging: keys (chunk-swizzled), f16 weight tables, w2 ----
    {
        const char* ksrc = (const char*)(keys + (size_t)b * (T_DIM * 64));
        #pragma unroll 4
        for (int i = tid; i < T_DIM * 16; i += 256) {
            int r = i >> 4, c = i & 15;
            int cs = c ^ (r & 7);
            asm volatile("cp.async.cg.shared.global [%0], [%1], 16;"
                         :: "r"(sbase + OFF_K + r * 256 + cs * 16), "l"(ksrc + i * 16));
        }
        #pragma unroll
        for (int i = tid; i < 256; i += 256) {
            asm volatile("cp.async.cg.shared.global [%0], [%1], 16;"
                         :: "r"(sbase + OFF_WHI + i * 16), "l"((const char*)g_whi + i * 16));
            asm volatile("cp.async.cg.shared.global [%0], [%1], 16;"
                         :: "r"(sbase + OFF_WLO + i * 16), "l"((const char*)g_wlo + i * 16));
        }
        if (tid < 8)
            asm volatile("cp.async.cg.shared.global [%0], [%1], 16;"
                         :: "r"(sbase + OFF_W2 + tid * 16),
                            "l"((const char*)W2 + tid * 16));
        asm volatile("cp.async.commit_group;" ::: "memory");
    }

    // ---- overlapped: per-CTA qh chain (warp 0, reads g_wq from L2) ----
    if (wid == 0) {
        float q0 = query[b * 64 + lane];
        float q1 = query[b * 64 + 32 + lane];
        float s = b1[lane];
        #pragma unroll
        for (int d = 0; d < 32; d++)
            s = fmaf(__shfl_sync(0xffffffffu, q0, d), g_wq[d * 32 + lane], s);
        #pragma unroll
        for (int d = 0; d < 32; d++)
            s = fmaf(__shfl_sync(0xffffffffu, q1, d), g_wq[(32 + d) * 32 + lane], s);
        smf[OFF_QH / 4 + lane] = s;
    }

    // ---- overlapped: mask dtype detect + per-thread mask prefetch + b2 ----
    int my_nz = 0;
    #pragma unroll
    for (int w = lane; w < 256; w += 32)
        my_nz |= mask_raw[4 * w + 1] | mask_raw[4 * w + 2] | mask_raw[4 * w + 3];
    const bool mode_u8 = __any_sync(0xffffffffu, my_nz != 0);
    const int* mask_i32 = (const int*)mask_raw;
    const float b2v = __ldg(b2);

    int mval = 0;
    if (t4 == 0) {
        #pragma unroll
        for (int mi = 0; mi < 2; mi++) {
            if (mi == 1 && wid >= 5) continue;
            const int m0 = (wid + 8 * mi) * 16;
            const int r0 = m0 + g, r1 = r0 + 8;
            bool v0 = mode_u8 ? (mask_raw[b * T_DIM + r0] != 0)
                              : (mask_i32[b * T_DIM + r0] != 0);
            mval |= (int)v0 << (2 * mi);
            if (r1 < T_DIM) {
                bool v1 = mode_u8 ? (mask_raw[b * T_DIM + r1] != 0)
                                  : (mask_i32[b * T_DIM + r1] != 0);
                mval |= (int)v1 << (2 * mi + 1);
            }
        }
    }

    asm volatile("cp.async.wait_group 0;" ::: "memory");
    __syncthreads();

    // ====== score GEMM via mma.sync m16n8k16 f16, w hi/lo 2-product split ======
    float acc[2][4][4];
    #pragma unroll
    for (int mi = 0; mi < 2; mi++)
        #pragma unroll
        for (int nt = 0; nt < 4; nt++)
            #pragma unroll
            for (int e = 0; e < 4; e++) acc[mi][nt][e] = 0.0f;

    const uint32_t wb = sbase + (uint32_t)(t4 * 256 + g * 8);
    #pragma unroll
    for (int ks = 0; ks < 4; ks++) {
        uint32_t bh[4][2], bl[4][2];
        #pragma unroll
        for (int nt = 0; nt < 4; nt++) {
            asm("ld.shared.v2.u32 {%0,%1},[%2];"
                : "=r"(bh[nt][0]), "=r"(bh[nt][1])
                : "r"(wb + OFF_WHI + ks * 1024 + nt * 64));
            asm("ld.shared.v2.u32 {%0,%1},[%2];"
                : "=r"(bl[nt][0]), "=r"(bl[nt][1])
                : "r"(wb + OFF_WLO + ks * 1024 + nt * 64));
        }
        #pragma unroll
        for (int mi = 0; mi < 2; mi++) {
            if (mi == 1 && wid >= 5) continue;
            const int m0 = (wid + 8 * mi) * 16;
            const uint32_t base0 = sbase + OFF_K +
                                   (uint32_t)((m0 + g) * 256 + ((t4 & 1) << 3));
            const int c0 = 4 * ks + (t4 >> 1);
            const uint32_t o0 = (uint32_t)((c0 ^ g) << 4);
            const uint32_t o2 = (uint32_t)(((c0 + 2) ^ g) << 4);
            float2 A0, A2;
            asm("ld.shared.v2.f32 {%0,%1},[%2];" : "=f"(A0.x), "=f"(A0.y) : "r"(base0 + o0));
            asm("ld.shared.v2.f32 {%0,%1},[%2];" : "=f"(A2.x), "=f"(A2.y) : "r"(base0 + o2));
            uint32_t a0, a1, a2, a3;
            asm("cvt.rn.f16x2.f32 %0,%1,%2;" : "=r"(a0) : "f"(A0.y), "f"(A0.x));
            asm("cvt.rn.f16x2.f32 %0,%1,%2;" : "=r"(a2) : "f"(A2.y), "f"(A2.x));
            if ((m0 + g + 8) < T_DIM) {
                float2 A1, A3;
                asm("ld.shared.v2.f32 {%0,%1},[%2];"
                    : "=f"(A1.x), "=f"(A1.y) : "r"(base0 + 2048 + o0));
                asm("ld.shared.v2.f32 {%0,%1},[%2];"
                    : "=f"(A3.x), "=f"(A3.y) : "r"(base0 + 2048 + o2));
                asm("cvt.rn.f16x2.f32 %0,%1,%2;" : "=r"(a1) : "f"(A1.y), "f"(A1.x));
                asm("cvt.rn.f16x2.f32 %0,%1,%2;" : "=r"(a3) : "f"(A3.y), "f"(A3.x));
            } else { a1 = 0u; a3 = 0u; }
            #pragma unroll
            for (int nt = 0; nt < 4; nt++) {
                asm volatile(
                    "mma.sync.aligned.m16n8k16.row.col.f32.f16.f16.f32 "
                    "{%0,%1,%2,%3}, {%4,%5,%6,%7}, {%8,%9}, {%0,%1,%2,%3};"
                    : "+f"(acc[mi][nt][0]), "+f"(acc[mi][nt][1]),
                      "+f"(acc[mi][nt][2]), "+f"(acc[mi][nt][3])
                    : "r"(a0), "r"(a1), "r"(a2), "r"(a3),
                      "r"(bh[nt][0]), "r"(bh[nt][1]));
                asm volatile(
                    "mma.sync.aligned.m16n8k16.row.col.f32.f16.f16.f32 "
                    "{%0,%1,%2,%3}, {%4,%5,%6,%7}, {%8,%9}, {%0,%1,%2,%3};"
                    : "+f"(acc[mi][nt][0]), "+f"(acc[mi][nt][1]),
                      "+f"(acc[mi][nt][2]), "+f"(acc[mi][nt][3])
                    : "r"(a0), "r"(a1), "r"(a2), "r"(a3),
                      "r"(bl[nt][0]), "r"(bl[nt][1]));
            }
        }
    }

    // ---- epilogue: h = C + qh ; sigmoid; dot W2; reduce over t4; mask ----
    #pragma unroll
    for (int mi = 0; mi < 2; mi++) {
        if (mi == 1 && wid >= 5) continue;
        const int m0 = (wid + 8 * mi) * 16;
        float s_lo = 0.0f, s_hi = 0.0f;
        #pragma unroll
        for (int nt = 0; nt < 4; nt++) {
            const int j0 = 8 * nt + 2 * t4;
            float2 qh2 = *(float2*)(sm + OFF_QH + j0 * 4);
            float2 w22 = *(float2*)(sm + OFF_W2 + j0 * 4);
            s_lo = fmaf(sigmoidf_fast(acc[mi][nt][0] + qh2.x), w22.x, s_lo);
            s_lo = fmaf(sigmoidf_fast(acc[mi][nt][1] + qh2.y), w22.y, s_lo);
            s_hi = fmaf(sigmoidf_fast(acc[mi][nt][2] + qh2.x), w22.x, s_hi);
            s_hi = fmaf(sigmoidf_fast(acc[mi][nt][3] + qh2.y), w22.y, s_hi);
        }
        s_lo += __shfl_xor_sync(0xffffffffu, s_lo, 1);
        s_lo += __shfl_xor_sync(0xffffffffu, s_lo, 2);
        s_hi += __shfl_xor_sync(0xffffffffu, s_hi, 1);
        s_hi += __shfl_xor_sync(0xffffffffu, s_hi, 2);
        if (t4 == 0) {
            const int r0 = m0 + g, r1 = r0 + 8;
            smf[OFF_SC / 4 + r0] = ((mval >> (2 * mi)) & 1) ? (s_lo + b2v) : NEG_INF;
            if (r1 < T_DIM)
                smf[OFF_SC / 4 + r1] = ((mval >> (2 * mi + 1)) & 1) ? (s_hi + b2v) : NEG_INF;
        }
    }
    __syncthreads();

    // ---- softmax over 200 scores (warp 0) ----
    if (tid < 32) {
        float m = -1e38f;
        for (int t = lane; t < T_DIM; t += 32) m = fmaxf(m, smf[OFF_SC / 4 + t]);
        #pragma unroll
        for (int o = 16; o; o >>= 1) m = fmaxf(m, __shfl_xor_sync(0xffffffffu, m, o));
        float s = 0.0f;
        for (int t = lane; t < T_DIM; t += 32) {
            float e = __expf(smf[OFF_SC / 4 + t] - m);
            smf[OFF_SC / 4 + t] = e;
            s += e;
        }
        #pragma unroll
        for (int o = 16; o; o >>= 1) s += __shfl_xor_sync(0xffffffffu, s, o);
        if (lane == 0) smf[OFF_SINV / 4] = __fdividef(1.0f, s);
    }
    __syncthreads();

    // ---- weighted key sum, f32x2 over d-pairs: warp w handles keys [25w, 25w+25) ----
    {
        const int part = tid >> 5;
        unsigned long long acw = 0ull;
        const uint32_t kbase = sbase + OFF_K;
        const int t0 = part * 25;
        #pragma unroll 5
        for (int t = t0; t < t0 + 25; t++) {
            float p = smf[OFF_SC / 4 + t];
            unsigned long long pd;
            asm("mov.b64 %0,{%1,%1};" : "=l"(pd) : "r"(__float_as_uint(p)));
            int gs = (lane >> 1) ^ (t & 7);
            unsigned long long kv;
            asm("ld.shared.b64 %0,[%1];" : "=l"(kv)
                : "r"(kbase + t * 256 + (gs << 4) + ((lane & 1) << 3)));
            asm("fma.rn.f32x2 %0,%1,%2,%0;" : "+l"(acw) : "l"(kv), "l"(pd));
        }
        asm volatile("st.shared.b64 [%0],%1;"
                     :: "r"(sbase + OFF_OP + part * 256 + lane * 8), "l"(acw));
    }
    __syncthreads();
    if (tid < 64) {
        float r = 0.0f;
        #pragma unroll
        for (int p = 0; p < 8; p++)
            r += smf[(OFF_OP + p * 256) / 4 + tid];
        out[b * 64 + tid] = r * smf[OFF_SINV / 4];
    }
}

extern "C" void kernel_launch(void* const* d_in, const int* in_sizes, int n_in,
                              void* d_out, int out_size)
{
    const float*         query = (const float*)d_in[0];
    const float*         keys  = (const float*)d_in[1];
    const unsigned char* mask  = (const unsigned char*)d_in[2];
    const float*         W1    = (const float*)d_in[3];
    const float*         b1    = (const float*)d_in[4];
    const float*         W2    = (const float*)d_in[5];
    const float*         b2    = (const float*)d_in[6];
    float* out = (float*)d_out;

    setup_kernel<<<1, 256>>>(W1);
    cudaFuncSetAttribute(attn_pool_kernel,
                         cudaFuncAttributeMaxDynamicSharedMemorySize, SMEM_BYTES);
    attn_pool_kernel<<<B_DIM, 256, SMEM_BYTES>>>(query, keys, mask, b1, W2, b2, out);
}

// round 9
// speedup vs baseline: 1.4520x; 1.0706x over previous
#include <cuda_runtime.h>
#include <cuda_fp16.h>
#include <cstdint>

#define B_DIM 4096
#define T_DIM 200
#define NEG_INF (-4294967295.0f)

// dynamic smem byte offsets
#define OFF_K    0        // f32 K[200][64]; 16B-chunk XOR swizzle: chunk' = chunk ^ (row&7)
#define OFF_QH   51200    // f32 qh[32]
#define OFF_W2   51328    // f32 w2[32]
#define OFF_SC   51456    // f32 scores[200] (pad to 832)
#define OFF_RED  52288    // f32 red[16]: [0..7] max partials, [8..15] sum partials
#define OFF_OP   52416    // u64 opart[8][32] f32x2 partials
#define OFF_SINV 54464    // (unused spare)
#define SMEM_BYTES 54480

__device__ float    g_wq[2048];    // W1a + W1c  (qh chain, read from L2)
__device__ uint32_t g_whi[1024];   // f16x2-packed fused weights, mma B-fragment order
__device__ uint32_t g_wlo[1024];   // f16 residuals

// ---------------- setup kernel: weight tables, 12 blocks ----------------
__global__ __launch_bounds__(256)
void setup_kernel(const float* __restrict__ W1)
{
    const int tid = threadIdx.x, blk = blockIdx.x;
    if (blk < 8) {
        const int i = blk * 256 + tid;
        g_wq[i] = W1[i] + W1[4096 + i];
        return;
    }
    const int idx = (blk - 8) * 256 + tid;
    int d2 = idx >> 5, j = idx & 31, k = 2 * d2;
    float w0 = W1[2048 + k * 32 + j] - W1[4096 + k * 32 + j];
    float w1 = W1[2048 + (k + 1) * 32 + j] - W1[4096 + (k + 1) * 32 + j];
    uint32_t hi, lo;
    asm("cvt.rn.f16x2.f32 %0, %1, %2;" : "=r"(hi) : "f"(w1), "f"(w0));
    float h0f = __half2float(__ushort_as_half((unsigned short)(hi & 0xFFFFu)));
    float h1f = __half2float(__ushort_as_half((unsigned short)(hi >> 16)));
    asm("cvt.rn.f16x2.f32 %0, %1, %2;" : "=r"(lo) : "f"(w1 - h1f), "f"(w0 - h0f));
    int ks = d2 >> 3, k2 = d2 & 7, t4 = k2 & 3, sel = k2 >> 2;
    int word = ((ks * 4 + t4) * 32 + j) * 2 + sel;
    g_whi[word] = hi;
    g_wlo[word] = lo;
}

static __device__ __forceinline__ float sigmoidf_fast(float h) {
    return __fdividef(1.0f, 1.0f + __expf(-h));
}

// ---------------- main kernel ----------------
__global__ __launch_bounds__(256, 4)
void attn_pool_kernel(const float* __restrict__ query,
                      const float* __restrict__ keys,
                      const unsigned char* __restrict__ mask_raw,
                      const float* __restrict__ b1,
                      const float* __restrict__ W2,
                      const float* __restrict__ b2,
                      float* __restrict__ out)
{
    extern __shared__ char sm[];
    float* smf = (float*)sm;
    const int b    = blockIdx.x;
    const int tid  = threadIdx.x;
    const int lane = tid & 31;
    const int wid  = tid >> 5;
    const int g    = lane >> 2;      // fragment group id
    const int t4   = lane & 3;       // thread-in-group
    uint32_t sbase;
    asm("{ .reg .u64 t; cvta.to.shared.u64 t, %1; cvt.u32.u64 %0, t; }"
        : "=r"(sbase) : "l"(sm));

    // ---- async staging: keys (chunk-swizzled), w2 ----
    {
        const char* ksrc = (const char*)(keys + (size_t)b * (T_DIM * 64));
        #pragma unroll 4
        for (int i = tid; i < T_DIM * 16; i += 256) {
            int r = i >> 4, c = i & 15;
            int cs = c ^ (r & 7);
            asm volatile("cp.async.cg.shared.global [%0], [%1], 16;"
                         :: "r"(sbase + OFF_K + r * 256 + cs * 16), "l"(ksrc + i * 16));
        }
        if (tid < 8)
            asm volatile("cp.async.cg.shared.global [%0], [%1], 16;"
                         :: "r"(sbase + OFF_W2 + tid * 16),
                            "l"((const char*)W2 + tid * 16));
        asm volatile("cp.async.commit_group;" ::: "memory");
    }

    // ---- overlapped: per-CTA qh chain (warp 0, reads g_wq from L2) ----
    if (wid == 0) {
        float q0 = query[b * 64 + lane];
        float q1 = query[b * 64 + 32 + lane];
        float s = b1[lane];
        #pragma unroll
        for (int d = 0; d < 32; d++)
            s = fmaf(__shfl_sync(0xffffffffu, q0, d), g_wq[d * 32 + lane], s);
        #pragma unroll
        for (int d = 0; d < 32; d++)
            s = fmaf(__shfl_sync(0xffffffffu, q1, d), g_wq[(32 + d) * 32 + lane], s);
        smf[OFF_QH / 4 + lane] = s;
    }

    // ---- overlapped: mask dtype detect + per-thread mask prefetch + b2 ----
    int my_nz = 0;
    #pragma unroll
    for (int w = lane; w < 256; w += 32)
        my_nz |= mask_raw[4 * w + 1] | mask_raw[4 * w + 2] | mask_raw[4 * w + 3];
    const bool mode_u8 = __any_sync(0xffffffffu, my_nz != 0);
    const int* mask_i32 = (const int*)mask_raw;
    const float b2v = __ldg(b2);

    int mval = 0;
    if (t4 == 0) {
        #pragma unroll
        for (int mi = 0; mi < 2; mi++) {
            if (mi == 1 && wid >= 5) continue;
            const int m0 = (wid + 8 * mi) * 16;
            const int r0 = m0 + g, r1 = r0 + 8;
            bool v0 = mode_u8 ? (mask_raw[b * T_DIM + r0] != 0)
                              : (mask_i32[b * T_DIM + r0] != 0);
            mval |= (int)v0 << (2 * mi);
            if (r1 < T_DIM) {
                bool v1 = mode_u8 ? (mask_raw[b * T_DIM + r1] != 0)
                                  : (mask_i32[b * T_DIM + r1] != 0);
                mval |= (int)v1 << (2 * mi + 1);
            }
        }
    }

    asm volatile("cp.async.wait_group 0;" ::: "memory");
    __syncthreads();

    // ====== score GEMM via mma.sync m16n8k16 f16; B fragments streamed from L2 ======
    float acc[2][4][4];
    #pragma unroll
    for (int mi = 0; mi < 2; mi++)
        #pragma unroll
        for (int nt = 0; nt < 4; nt++)
            #pragma unroll
            for (int e = 0; e < 4; e++) acc[mi][nt][e] = 0.0f;

    const uint32_t wofs = (uint32_t)(t4 * 64 + g * 2);   // word offset in g_whi/g_wlo
    #pragma unroll
    for (int ks = 0; ks < 4; ks++) {
        uint2 bh[4], bl[4];
        #pragma unroll
        for (int nt = 0; nt < 4; nt++) {
            bh[nt] = __ldg((const uint2*)(g_whi + wofs + ks * 256 + nt * 16));
            bl[nt] = __ldg((const uint2*)(g_wlo + wofs + ks * 256 + nt * 16));
        }
        #pragma unroll
        for (int mi = 0; mi < 2; mi++) {
            if (mi == 1 && wid >= 5) continue;
            const int m0 = (wid + 8 * mi) * 16;
            const uint32_t base0 = sbase + OFF_K +
                                   (uint32_t)((m0 + g) * 256 + ((t4 & 1) << 3));
            const int c0 = 4 * ks + (t4 >> 1);
            const uint32_t o0 = (uint32_t)((c0 ^ g) << 4);
            const uint32_t o2 = (uint32_t)(((c0 + 2) ^ g) << 4);
            float2 A0, A2;
            asm("ld.shared.v2.f32 {%0,%1},[%2];" : "=f"(A0.x), "=f"(A0.y) : "r"(base0 + o0));
            asm("ld.shared.v2.f32 {%0,%1},[%2];" : "=f"(A2.x), "=f"(A2.y) : "r"(base0 + o2));
            uint32_t a0, a1, a2, a3;
            asm("cvt.rn.f16x2.f32 %0,%1,%2;" : "=r"(a0) : "f"(A0.y), "f"(A0.x));
            asm("cvt.rn.f16x2.f32 %0,%1,%2;" : "=r"(a2) : "f"(A2.y), "f"(A2.x));
            if ((m0 + g + 8) < T_DIM) {
                float2 A1, A3;
                asm("ld.shared.v2.f32 {%0,%1},[%2];"
                    : "=f"(A1.x), "=f"(A1.y) : "r"(base0 + 2048 + o0));
                asm("ld.shared.v2.f32 {%0,%1},[%2];"
                    : "=f"(A3.x), "=f"(A3.y) : "r"(base0 + 2048 + o2));
                asm("cvt.rn.f16x2.f32 %0,%1,%2;" : "=r"(a1) : "f"(A1.y), "f"(A1.x));
                asm("cvt.rn.f16x2.f32 %0,%1,%2;" : "=r"(a3) : "f"(A3.y), "f"(A3.x));
            } else { a1 = 0u; a3 = 0u; }
            #pragma unroll
            for (int nt = 0; nt < 4; nt++) {
                asm volatile(
                    "mma.sync.aligned.m16n8k16.row.col.f32.f16.f16.f32 "
                    "{%0,%1,%2,%3}, {%4,%5,%6,%7}, {%8,%9}, {%0,%1,%2,%3};"
                    : "+f"(acc[mi][nt][0]), "+f"(acc[mi][nt][1]),
                      "+f"(acc[mi][nt][2]), "+f"(acc[mi][nt][3])
                    : "r"(a0), "r"(a1), "r"(a2), "r"(a3),
                      "r"(bh[nt].x), "r"(bh[nt].y));
                asm volatile(
                    "mma.sync.aligned.m16n8k16.row.col.f32.f16.f16.f32 "
                    "{%0,%1,%2,%3}, {%4,%5,%6,%7}, {%8,%9}, {%0,%1,%2,%3};"
                    : "+f"(acc[mi][nt][0]), "+f"(acc[mi][nt][1]),
                      "+f"(acc[mi][nt][2]), "+f"(acc[mi][nt][3])
                    : "r"(a0), "r"(a1), "r"(a2), "r"(a3),
                      "r"(bl[nt].x), "r"(bl[nt].y));
            }
        }
    }

    // ---- epilogue: h = C + qh ; sigmoid; dot W2; reduce over t4; mask ----
    #pragma unroll
    for (int mi = 0; mi < 2; mi++) {
        if (mi == 1 && wid >= 5) continue;
        const int m0 = (wid + 8 * mi) * 16;
        float s_lo = 0.0f, s_hi = 0.0f;
        #pragma unroll
        for (int nt = 0; nt < 4; nt++) {
            const int j0 = 8 * nt + 2 * t4;
            float2 qh2 = *(float2*)(sm + OFF_QH + j0 * 4);
            float2 w22 = *(float2*)(sm + OFF_W2 + j0 * 4);
            s_lo = fmaf(sigmoidf_fast(acc[mi][nt][0] + qh2.x), w22.x, s_lo);
            s_lo = fmaf(sigmoidf_fast(acc[mi][nt][1] + qh2.y), w22.y, s_lo);
            s_hi = fmaf(sigmoidf_fast(acc[mi][nt][2] + qh2.x), w22.x, s_hi);
            s_hi = fmaf(sigmoidf_fast(acc[mi][nt][3] + qh2.y), w22.y, s_hi);
        }
        s_lo += __shfl_xor_sync(0xffffffffu, s_lo, 1);
        s_lo += __shfl_xor_sync(0xffffffffu, s_lo, 2);
        s_hi += __shfl_xor_sync(0xffffffffu, s_hi, 1);
        s_hi += __shfl_xor_sync(0xffffffffu, s_hi, 2);
        if (t4 == 0) {
            const int r0 = m0 + g, r1 = r0 + 8;
            smf[OFF_SC / 4 + r0] = ((mval >> (2 * mi)) & 1) ? (s_lo + b2v) : NEG_INF;
            if (r1 < T_DIM)
                smf[OFF_SC / 4 + r1] = ((mval >> (2 * mi + 1)) & 1) ? (s_hi + b2v) : NEG_INF;
        }
    }
    __syncthreads();

    // ---- parallel softmax: warp w owns scores [25w, 25w+25) ----
    const int t0 = wid * 25;
    {
        float m = -1e38f;
        if (lane < 25) m = smf[OFF_SC / 4 + t0 + lane];
        #pragma unroll
        for (int o = 16; o; o >>= 1) m = fmaxf(m, __shfl_xor_sync(0xffffffffu, m, o));
        if (lane == 0) smf[OFF_RED / 4 + wid] = m;
    }
    __syncthreads();
    float sinv;
    {
        float gm = smf[OFF_RED / 4];
        #pragma unroll
        for (int p = 1; p < 8; p++) gm = fmaxf(gm, smf[OFF_RED / 4 + p]);
        float e = 0.0f;
        if (lane < 25) {
            e = __expf(smf[OFF_SC / 4 + t0 + lane] - gm);
            smf[OFF_SC / 4 + t0 + lane] = e;
        }
        float s = e;
        #pragma unroll
        for (int o = 16; o; o >>= 1) s += __shfl_xor_sync(0xffffffffu, s, o);
        if (lane == 0) smf[OFF_RED / 4 + 8 + wid] = s;
        __syncthreads();
        float gs = smf[OFF_RED / 4 + 8];
        #pragma unroll
        for (int p = 1; p < 8; p++) gs += smf[OFF_RED / 4 + 8 + p];
        sinv = __fdividef(1.0f, gs);
    }

    // ---- weighted key sum, f32x2 over d-pairs: warp w handles keys [25w, 25w+25) ----
    {
        unsigned long long acw = 0ull;
        const uint32_t kbase = sbase + OFF_K;
        #pragma unroll 5
        for (int t = t0; t < t0 + 25; t++) {
            float p = smf[OFF_SC / 4 + t];
            unsigned long long pd;
            asm("mov.b64 %0,{%1,%1};" : "=l"(pd) : "r"(__float_as_uint(p)));
            int gs2 = (lane >> 1) ^ (t & 7);
            unsigned long long kv;
            asm("ld.shared.b64 %0,[%1];" : "=l"(kv)
                : "r"(kbase + t * 256 + (gs2 << 4) + ((lane & 1) << 3)));
            asm("fma.rn.f32x2 %0,%1,%2,%0;" : "+l"(acw) : "l"(kv), "l"(pd));
        }
        unsigned long long sd;
        asm("mov.b64 %0,{%1,%1};" : "=l"(sd) : "r"(__float_as_uint(sinv)));
        unsigned long long zero = 0ull, scaled;
        asm("fma.rn.f32x2 %0,%1,%2,%3;" : "=l"(scaled) : "l"(acw), "l"(sd), "l"(zero));
        asm volatile("st.shared.b64 [%0],%1;"
                     :: "r"(sbase + OFF_OP + wid * 256 + lane * 8), "l"(scaled));
    }
    __syncthreads();
    if (tid < 64) {
        float r = 0.0f;
        #pragma unroll
        for (int p = 0; p < 8; p++)
            r += smf[(OFF_OP + p * 256) / 4 + tid];
        out[b * 64 + tid] = r;
    }
}

extern "C" void kernel_launch(void* const* d_in, const int* in_sizes, int n_in,
                              void* d_out, int out_size)
{
    const float*         query = (const float*)d_in[0];
    const float*         keys  = (const float*)d_in[1];
    const unsigned char* mask  = (const unsigned char*)d_in[2];
    const float*         W1    = (const float*)d_in[3];
    const float*         b1    = (const float*)d_in[4];
    const float*         W2    = (const float*)d_in[5];
    const float*         b2    = (const float*)d_in[6];
    float* out = (float*)d_out;

    setup_kernel<<<12, 256>>>(W1);
    cudaFuncSetAttribute(attn_pool_kernel,
                         cudaFuncAttributeMaxDynamicSharedMemorySize, SMEM_BYTES);
    attn_pool_kernel<<<B_DIM, 256, SMEM_BYTES>>>(query, keys, mask, b1, W2, b2, out);
}